// round 13
// baseline (speedup 1.0000x reference)
#include <cuda_runtime.h>
#include <cstdint>

#define HNUM 12
#define NTOK 2048
#define DMODEL 768
#define PD 64
#define BATCH 2
#define ODSZ (BATCH * HNUM * NTOK * PD)
#define LSZ (BATCH * HNUM * NTOK)

// scratch (device globals — no allocations allowed)
static __device__ float g_Q[ODSZ];   // column-pair permuted, see perm8()
static __device__ float g_K[ODSZ];   // column-pair permuted
static __device__ float g_V[ODSZ];   // pre-rounded to tf32
static __device__ float g_Opart[2 * ODSZ];
static __device__ float g_lpart[2 * LSZ];

__device__ __forceinline__ uint32_t f2tf(float x) {
    uint32_t u;
    asm("cvt.rna.tf32.f32 %0, %1;" : "=r"(u) : "f"(x));
    return u;
}
// exact split: hi = x with low 13 mantissa bits cleared (valid tf32), lo = x - hi (exact)
__device__ __forceinline__ float trunc_hi(float x) {
    return __uint_as_float(__float_as_uint(x) & 0xFFFFE000u);
}
__device__ __forceinline__ float ex2f(float x) {
    float r;
    asm("ex2.approx.f32 %0, %1;" : "=f"(r) : "f"(x));
    return r;
}
// perm within 8-col group: orig col c sits at position 2*(c&3) + (c>>2)
// => orig pair (c, c+4), c<4, lands at adjacent positions (2c, 2c+1).
__device__ __forceinline__ int perm8(int d) {
    return (d & ~7) | (((d & 3) << 1) | ((d >> 2) & 1));
}

__device__ __forceinline__ void mma8(float c[4], uint32_t a0, uint32_t a1, uint32_t a2, uint32_t a3,
                                     uint32_t b0, uint32_t b1) {
    asm volatile(
        "mma.sync.aligned.m16n8k8.row.col.f32.tf32.tf32.f32 "
        "{%0,%1,%2,%3},{%4,%5,%6,%7},{%8,%9},{%0,%1,%2,%3};\n"
        : "+f"(c[0]), "+f"(c[1]), "+f"(c[2]), "+f"(c[3])
        : "r"(a0), "r"(a1), "r"(a2), "r"(a3), "r"(b0), "r"(b1));
}

__device__ __forceinline__ uint32_t s2u(const void* p) {
    uint32_t a;
    asm("{ .reg .u64 t; cvta.to.shared.u64 t, %1; cvt.u32.u64 %0, t; }" : "=r"(a) : "l"(p));
    return a;
}
#define CP_ASYNC16(sa, ga) \
    asm volatile("cp.async.cg.shared.global [%0], [%1], 16;" :: "r"(sa), "l"(ga) : "memory")
#define CP_COMMIT() asm volatile("cp.async.commit_group;" ::: "memory")
#define CP_WAIT0() asm volatile("cp.async.wait_group 0;" ::: "memory")

// ===================== projection: cp.async double-buffer, 3 CTAs/SM ========
#define PX(buf, r, c) ((buf) * 4608 + (r) * 36 + (c))
#define PW(buf, r, c) (9216 + (buf) * 2304 + (r) * 36 + (c))
#define PROJ_SMEM_FLOATS (9216 + 4608)
__global__ __launch_bounds__(128, 3) void proj_kernel(const float* __restrict__ X2,
                                                      const float* __restrict__ X1,
                                                      const float* __restrict__ Wq,
                                                      const float* __restrict__ bq,
                                                      const float* __restrict__ Wkv,
                                                      const float* __restrict__ bkv) {
    extern __shared__ float ps[];
    const int tid = threadIdx.x;
    const int w = tid >> 5;
    const int lane = tid & 31;
    const int r0 = lane >> 2;
    const int q4 = lane & 3;
    const int m0 = blockIdx.x * 128;

    const int yb = blockIdx.y;
    const bool isQ = (yb < 12);
    const float* __restrict__ X = isQ ? X2 : X1;
    const float* __restrict__ W = isQ ? Wq : Wkv;
    const float* __restrict__ bias = isQ ? bq : bkv;
    const int n0 = isQ ? (yb * 64) : ((yb - 12) * 64);
    const bool is_v = (!isQ) && (n0 >= DMODEL);

    const uint32_t smem_u = s2u(ps);

    auto issue_chunk = [&](int kc, int buf) {
#pragma unroll
        for (int it = 0; it < 8; ++it) {
            int idx4 = tid + it * 128;
            int r = idx4 >> 3;
            int c4 = (idx4 & 7) * 4;
            CP_ASYNC16(smem_u + PX(buf, r, c4) * 4, &X[(m0 + r) * DMODEL + kc + c4]);
        }
#pragma unroll
        for (int it = 0; it < 4; ++it) {
            int idx4 = tid + it * 128;
            int r = idx4 >> 3;
            int c4 = (idx4 & 7) * 4;
            CP_ASYNC16(smem_u + PW(buf, r, c4) * 4, &W[(n0 + r) * DMODEL + kc + c4]);
        }
        CP_COMMIT();
    };

    issue_chunk(0, 0);

    float acc[2][8][4];
#pragma unroll
    for (int t = 0; t < 2; ++t)
#pragma unroll
        for (int i = 0; i < 8; ++i) {
            acc[t][i][0] = 0.f; acc[t][i][1] = 0.f; acc[t][i][2] = 0.f; acc[t][i][3] = 0.f;
        }

    int buf = 0;
    for (int kc = 0; kc < DMODEL; kc += 32) {
        CP_WAIT0();
        __syncthreads();
        if (kc + 32 < DMODEL) issue_chunk(kc + 32, buf ^ 1);

        if (!is_v) {
#pragma unroll
            for (int kk = 0; kk < 4; ++kk) {
                const int k0 = kk * 8 + q4;
                uint32_t ah[2][4], al[2][4];
#pragma unroll
                for (int t = 0; t < 2; ++t) {
                    const int rowA = w * 32 + t * 16 + r0;
                    float a0f = ps[PX(buf, rowA, k0)];
                    float a1f = ps[PX(buf, rowA + 8, k0)];
                    float a2f = ps[PX(buf, rowA, k0 + 4)];
                    float a3f = ps[PX(buf, rowA + 8, k0 + 4)];
                    float h0 = trunc_hi(a0f), h1 = trunc_hi(a1f), h2 = trunc_hi(a2f), h3 = trunc_hi(a3f);
                    ah[t][0] = __float_as_uint(h0); al[t][0] = __float_as_uint(a0f - h0);
                    ah[t][1] = __float_as_uint(h1); al[t][1] = __float_as_uint(a1f - h1);
                    ah[t][2] = __float_as_uint(h2); al[t][2] = __float_as_uint(a2f - h2);
                    ah[t][3] = __float_as_uint(h3); al[t][3] = __float_as_uint(a3f - h3);
                }
#pragma unroll
                for (int nt = 0; nt < 8; ++nt) {
                    float b0f = ps[PW(buf, nt * 8 + r0, k0)];
                    float b1f = ps[PW(buf, nt * 8 + r0, k0 + 4)];
                    float bh0f = trunc_hi(b0f), bh1f = trunc_hi(b1f);
                    uint32_t bh0 = __float_as_uint(bh0f), bh1 = __float_as_uint(bh1f);
                    uint32_t bl0 = __float_as_uint(b0f - bh0f), bl1 = __float_as_uint(b1f - bh1f);
#pragma unroll
                    for (int t = 0; t < 2; ++t) {
                        mma8(acc[t][nt], al[t][0], al[t][1], al[t][2], al[t][3], bh0, bh1);
                        mma8(acc[t][nt], ah[t][0], ah[t][1], ah[t][2], ah[t][3], bl0, bl1);
                        mma8(acc[t][nt], ah[t][0], ah[t][1], ah[t][2], ah[t][3], bh0, bh1);
                    }
                }
            }
        } else {
#pragma unroll
            for (int kk = 0; kk < 4; ++kk) {
                const int k0 = kk * 8 + q4;
                uint32_t ah[2][4];
#pragma unroll
                for (int t = 0; t < 2; ++t) {
                    const int rowA = w * 32 + t * 16 + r0;
                    ah[t][0] = f2tf(ps[PX(buf, rowA, k0)]);
                    ah[t][1] = f2tf(ps[PX(buf, rowA + 8, k0)]);
                    ah[t][2] = f2tf(ps[PX(buf, rowA, k0 + 4)]);
                    ah[t][3] = f2tf(ps[PX(buf, rowA + 8, k0 + 4)]);
                }
#pragma unroll
                for (int nt = 0; nt < 8; ++nt) {
                    uint32_t bh0 = f2tf(ps[PW(buf, nt * 8 + r0, k0)]);
                    uint32_t bh1 = f2tf(ps[PW(buf, nt * 8 + r0, k0 + 4)]);
#pragma unroll
                    for (int t = 0; t < 2; ++t)
                        mma8(acc[t][nt], ah[t][0], ah[t][1], ah[t][2], ah[t][3], bh0, bh1);
                }
            }
        }
        buf ^= 1;
    }

    const int c0 = q4 * 2;
#pragma unroll
    for (int nt = 0; nt < 8; ++nt) {
        int n = n0 + nt * 8 + c0;
        float bias0 = bias[n];
        float bias1 = bias[n + 1];
        float* dst;
        int nn = n;
        if (isQ) {
            dst = g_Q;
        } else if (n < DMODEL) {
            dst = g_K;
        } else {
            dst = g_V;
            nn = n - DMODEL;
        }
        int hh = nn >> 6;
        int dd = nn & 63;
        int p0 = perm8(dd);
        int p1 = perm8(dd + 1);
#pragma unroll
        for (int t = 0; t < 2; ++t)
#pragma unroll
            for (int half = 0; half < 2; ++half) {
                int m = m0 + w * 32 + t * 16 + r0 + half * 8;
                int btk = m >> 11;
                int itok = m & (NTOK - 1);
                float v0 = acc[t][nt][half * 2 + 0] + bias0;
                float v1 = acc[t][nt][half * 2 + 1] + bias1;
                int idx = ((btk * HNUM + hh) * NTOK + itok) << 6;
                if (is_v) {
                    // V: pre-round to tf32 (bit-identical to rounding at attn load)
                    *reinterpret_cast<float2*>(&dst[idx + dd]) =
                        make_float2(__uint_as_float(f2tf(v0)), __uint_as_float(f2tf(v1)));
                } else {
                    // Q/K: column-pair permuted scalar stores
                    dst[idx + p0] = v0;
                    dst[idx + p1] = v1;
                }
            }
    }
}

// ===================== flash attention: split-K=2, LDS.64 fragments, preround V ==========
#define SSTRIDE 68
#define QROWS 128
#define KVBUF (64 * SSTRIDE)
__global__ __launch_bounds__(128, 2) void attn_kernel() {
    extern __shared__ float sm[];
    float* Qs = sm;  // 128 x 68 fp32 (permuted cols, scaled by log2e)

    const int tid = threadIdx.x;
    const int w = tid >> 5;
    const int lane = tid & 31;
    const int r0 = lane >> 2;
    const int q4 = lane & 3;
    const int zz = blockIdx.z;
    const int b = zz >> 1;
    const int kvhalf = zz & 1;
    const int h = blockIdx.y;
    const int i0 = blockIdx.x * QROWS;
    const int jbase = kvhalf * (NTOK / 2);

    const int base = ((b * HNUM + h) * NTOK) * PD;
    const float* __restrict__ Qg = g_Q + base;
    const float* __restrict__ Kg = g_K + base;
    const float* __restrict__ Vg = g_V + base;
    float* __restrict__ Og = g_Opart + kvhalf * ODSZ + base;
    float* __restrict__ Lg = g_lpart + kvhalf * LSZ + (b * HNUM + h) * NTOK;

    const uint32_t kv_u = s2u(sm) + QROWS * SSTRIDE * 4;

    auto issue_chunk = [&](int j0, int buf) {
        uint32_t kb = kv_u + (uint32_t)buf * (2 * KVBUF * 4);
#pragma unroll
        for (int it = 0; it < 8; ++it) {
            int idx4 = tid + it * 128;
            int r = idx4 >> 4;
            int c4 = (idx4 & 15) * 4;
            uint32_t so = (uint32_t)(r * SSTRIDE + c4) * 4;
            CP_ASYNC16(kb + so, &Kg[(j0 + r) * PD + c4]);
            // V rows permuted within each 8-block: smem row k holds key (k<4 ? 2k : 2k-7)
            int k = r & 7;
            int pr = (r & ~7) | ((k < 4) ? (k << 1) : ((k << 1) - 7));
            CP_ASYNC16(kb + KVBUF * 4 + so, &Vg[(j0 + pr) * PD + c4]);
        }
        CP_COMMIT();
    };

    issue_chunk(jbase, 0);

    const float LOG2E = 1.4426950408889634f;
    // stage Q tile (128 x 64) — g_Q already col-permuted; scale by log2e
#pragma unroll
    for (int it = 0; it < 16; ++it) {
        int idx4 = tid + it * 128;
        int r = idx4 >> 4;
        int c4 = (idx4 & 15) * 4;
        float4 qv = *reinterpret_cast<const float4*>(&Qg[(i0 + r) * PD + c4]);
        *reinterpret_cast<float4*>(&Qs[r * SSTRIDE + c4]) =
            make_float4(qv.x * LOG2E, qv.y * LOG2E, qv.z * LOG2E, qv.w * LOG2E);
    }

    float lr[4] = {0.f, 0.f, 0.f, 0.f};
    float Oacc[2][8][4];
#pragma unroll
    for (int t = 0; t < 2; ++t)
#pragma unroll
        for (int i = 0; i < 8; ++i) {
            Oacc[t][i][0] = 0.f; Oacc[t][i][1] = 0.f; Oacc[t][i][2] = 0.f; Oacc[t][i][3] = 0.f;
        }

    int buf = 0;
    for (int j0 = jbase; j0 < jbase + NTOK / 2; j0 += 64) {
        CP_WAIT0();
        __syncthreads();
        if (j0 + 64 < jbase + NTOK / 2) issue_chunk(j0 + 64, buf ^ 1);

        const float* Ks = sm + QROWS * SSTRIDE + buf * 2 * KVBUF;
        const float* Vs = Ks + KVBUF;

        // ---- S' = (log2e * Q) K^T : exact-split 3xTF32; LDS.64 fragments via col-perm ----
        float s[2][8][4];
#pragma unroll
        for (int t = 0; t < 2; ++t)
#pragma unroll
            for (int i = 0; i < 8; ++i) {
                s[t][i][0] = 0.f; s[t][i][1] = 0.f; s[t][i][2] = 0.f; s[t][i][3] = 0.f;
            }
#pragma unroll
        for (int kk = 0; kk < 8; ++kk) {
            const int kb = kk * 8 + 2 * q4;  // permuted: (orig q4, orig q4+4) adjacent
            uint32_t ah[2][4], al[2][4];
#pragma unroll
            for (int t = 0; t < 2; ++t) {
                const int rowA = w * 32 + t * 16 + r0;
                float2 A0 = *reinterpret_cast<const float2*>(&Qs[rowA * SSTRIDE + kb]);
                float2 A1 = *reinterpret_cast<const float2*>(&Qs[(rowA + 8) * SSTRIDE + kb]);
                float a0f = A0.x, a2f = A0.y, a1f = A1.x, a3f = A1.y;
                float h0 = trunc_hi(a0f), h1 = trunc_hi(a1f), h2 = trunc_hi(a2f), h3 = trunc_hi(a3f);
                ah[t][0] = __float_as_uint(h0); al[t][0] = __float_as_uint(a0f - h0);
                ah[t][1] = __float_as_uint(h1); al[t][1] = __float_as_uint(a1f - h1);
                ah[t][2] = __float_as_uint(h2); al[t][2] = __float_as_uint(a2f - h2);
                ah[t][3] = __float_as_uint(h3); al[t][3] = __float_as_uint(a3f - h3);
            }
#pragma unroll
            for (int nt = 0; nt < 8; ++nt) {
                float2 B = *reinterpret_cast<const float2*>(&Ks[(nt * 8 + r0) * SSTRIDE + kb]);
                float b0f = B.x, b1f = B.y;
                float bh0f = trunc_hi(b0f), bh1f = trunc_hi(b1f);
                uint32_t bh0 = __float_as_uint(bh0f), bh1 = __float_as_uint(bh1f);
                uint32_t bl0 = __float_as_uint(b0f - bh0f), bl1 = __float_as_uint(b1f - bh1f);
#pragma unroll
                for (int t = 0; t < 2; ++t) {
                    mma8(s[t][nt], al[t][0], al[t][1], al[t][2], al[t][3], bh0, bh1);
                    mma8(s[t][nt], ah[t][0], ah[t][1], ah[t][2], ah[t][3], bl0, bl1);
                    mma8(s[t][nt], ah[t][0], ah[t][1], ah[t][2], ah[t][3], bh0, bh1);
                }
            }
        }

        // ---- p = 2^(S'); accumulate row sums; P -> tf32 in registers ----
#pragma unroll
        for (int t = 0; t < 2; ++t) {
            float ps0 = 0.f, ps1 = 0.f;
#pragma unroll
            for (int nt = 0; nt < 8; ++nt) {
                float p0 = ex2f(s[t][nt][0]);
                float p1 = ex2f(s[t][nt][1]);
                float p2 = ex2f(s[t][nt][2]);
                float p3 = ex2f(s[t][nt][3]);
                ps0 += p0 + p1;
                ps1 += p2 + p3;
                s[t][nt][0] = __uint_as_float(f2tf(p0));
                s[t][nt][1] = __uint_as_float(f2tf(p1));
                s[t][nt][2] = __uint_as_float(f2tf(p2));
                s[t][nt][3] = __uint_as_float(f2tf(p3));
            }
            ps0 += __shfl_xor_sync(0xffffffffu, ps0, 1);
            ps0 += __shfl_xor_sync(0xffffffffu, ps0, 2);
            ps1 += __shfl_xor_sync(0xffffffffu, ps1, 1);
            ps1 += __shfl_xor_sync(0xffffffffu, ps1, 2);
            lr[2 * t] += ps0;
            lr[2 * t + 1] += ps1;
        }

        // ---- O += P V : A-frag IS the C-frag (V rows pre-permuted); V already tf32 ----
#pragma unroll
        for (int kk = 0; kk < 8; ++kk) {
#pragma unroll
            for (int dt = 0; dt < 8; ++dt) {
                uint32_t b0 = __float_as_uint(Vs[(kk * 8 + q4) * SSTRIDE + dt * 8 + r0]);
                uint32_t b1 = __float_as_uint(Vs[(kk * 8 + q4 + 4) * SSTRIDE + dt * 8 + r0]);
#pragma unroll
                for (int t = 0; t < 2; ++t)
                    mma8(Oacc[t][dt],
                         __float_as_uint(s[t][kk][0]), __float_as_uint(s[t][kk][2]),
                         __float_as_uint(s[t][kk][1]), __float_as_uint(s[t][kk][3]),
                         b0, b1);
            }
        }
        buf ^= 1;
    }

    // ---- epilogue: write unnormalized O and row sums l ----
#pragma unroll
    for (int t = 0; t < 2; ++t) {
        const int orow = i0 + w * 32 + t * 16 + r0;
        if (q4 == 0) {
            Lg[orow] = lr[2 * t];
            Lg[orow + 8] = lr[2 * t + 1];
        }
#pragma unroll
        for (int dt = 0; dt < 8; ++dt) {
            *reinterpret_cast<float2*>(&Og[orow * PD + dt * 8 + 2 * q4]) =
                make_float2(Oacc[t][dt][0], Oacc[t][dt][1]);
            *reinterpret_cast<float2*>(&Og[(orow + 8) * PD + dt * 8 + 2 * q4]) =
                make_float2(Oacc[t][dt][2], Oacc[t][dt][3]);
        }
    }
}

// ===================== combine: out = (O0 + O1) / (l0 + l1) ==============================
__global__ __launch_bounds__(256) void combine_kernel(float* __restrict__ out) {
    int idx4 = blockIdx.x * 256 + threadIdx.x;
    int fidx = idx4 * 4;
    int rowg = fidx >> 6;  // PD = 64
    float inv = 1.0f / (g_lpart[rowg] + g_lpart[LSZ + rowg]);
    float4 a = *reinterpret_cast<const float4*>(&g_Opart[fidx]);
    float4 c = *reinterpret_cast<const float4*>(&g_Opart[ODSZ + fidx]);
    *reinterpret_cast<float4*>(&out[fidx]) =
        make_float4((a.x + c.x) * inv, (a.y + c.y) * inv, (a.z + c.z) * inv, (a.w + c.w) * inv);
}

extern "C" void kernel_launch(void* const* d_in, const int* in_sizes, int n_in,
                              void* d_out, int out_size) {
    (void)in_sizes; (void)n_in; (void)out_size;
    const float* x1 = (const float*)d_in[0];
    const float* x2 = (const float*)d_in[1];
    const float* Wq = (const float*)d_in[2];
    const float* bq = (const float*)d_in[3];
    const float* Wkv = (const float*)d_in[4];
    const float* bkv = (const float*)d_in[5];
    float* out = (float*)d_out;

    const int proj_smem = PROJ_SMEM_FLOATS * sizeof(float);  // 55296
    cudaFuncSetAttribute(proj_kernel, cudaFuncAttributeMaxDynamicSharedMemorySize, proj_smem);
    cudaFuncSetAttribute(proj_kernel, cudaFuncAttributePreferredSharedMemoryCarveout, 100);
    proj_kernel<<<dim3(32, 36), 128, proj_smem>>>(x2, x1, Wq, bq, Wkv, bkv);

    const int smem_bytes = (QROWS * SSTRIDE + 4 * KVBUF) * sizeof(float);  // 104448
    cudaFuncSetAttribute(attn_kernel, cudaFuncAttributeMaxDynamicSharedMemorySize, smem_bytes);
    cudaFuncSetAttribute(attn_kernel, cudaFuncAttributePreferredSharedMemoryCarveout, 100);
    attn_kernel<<<dim3(NTOK / QROWS, HNUM, BATCH * 2), 128, smem_bytes>>>();

    combine_kernel<<<ODSZ / 4 / 256, 256>>>(out);
}

// round 14
// speedup vs baseline: 1.0888x; 1.0888x over previous
#include <cuda_runtime.h>
#include <cstdint>

#define HNUM 12
#define NTOK 2048
#define DMODEL 768
#define PD 64
#define BATCH 2
#define ODSZ (BATCH * HNUM * NTOK * PD)
#define LSZ (BATCH * HNUM * NTOK)

// scratch (device globals — no allocations allowed)
static __device__ float g_Q[ODSZ];
static __device__ float g_K[ODSZ];
static __device__ float g_V[ODSZ];   // pre-rounded to tf32 at proj store
static __device__ float g_Opart[2 * ODSZ];  // unnormalized O per KV-half
static __device__ float g_lpart[2 * LSZ];   // row sums per KV-half

__device__ __forceinline__ uint32_t f2tf(float x) {
    uint32_t u;
    asm("cvt.rna.tf32.f32 %0, %1;" : "=r"(u) : "f"(x));
    return u;
}
// exact split: hi = x with low 13 mantissa bits cleared (valid tf32), lo = x - hi (exact)
__device__ __forceinline__ float trunc_hi(float x) {
    return __uint_as_float(__float_as_uint(x) & 0xFFFFE000u);
}
__device__ __forceinline__ float ex2f(float x) {
    float r;
    asm("ex2.approx.f32 %0, %1;" : "=f"(r) : "f"(x));
    return r;
}

__device__ __forceinline__ void mma8(float c[4], uint32_t a0, uint32_t a1, uint32_t a2, uint32_t a3,
                                     uint32_t b0, uint32_t b1) {
    asm volatile(
        "mma.sync.aligned.m16n8k8.row.col.f32.tf32.tf32.f32 "
        "{%0,%1,%2,%3},{%4,%5,%6,%7},{%8,%9},{%0,%1,%2,%3};\n"
        : "+f"(c[0]), "+f"(c[1]), "+f"(c[2]), "+f"(c[3])
        : "r"(a0), "r"(a1), "r"(a2), "r"(a3), "r"(b0), "r"(b1));
}

__device__ __forceinline__ uint32_t s2u(const void* p) {
    uint32_t a;
    asm("{ .reg .u64 t; cvta.to.shared.u64 t, %1; cvt.u32.u64 %0, t; }" : "=r"(a) : "l"(p));
    return a;
}
#define CP_ASYNC16(sa, ga) \
    asm volatile("cp.async.cg.shared.global [%0], [%1], 16;" :: "r"(sa), "l"(ga) : "memory")
#define CP_COMMIT() asm volatile("cp.async.commit_group;" ::: "memory")
#define CP_WAIT0() asm volatile("cp.async.wait_group 0;" ::: "memory")

// ===================== projection: cp.async double-buffer, 4 CTAs/SM (R11 config) ========
#define PX(buf, r, c) ((buf) * 4608 + (r) * 36 + (c))
#define PW(buf, r, c) (9216 + (buf) * 2304 + (r) * 36 + (c))
#define PROJ_SMEM_FLOATS (9216 + 4608)
__global__ __launch_bounds__(128, 4) void proj_kernel(const float* __restrict__ X2,
                                                      const float* __restrict__ X1,
                                                      const float* __restrict__ Wq,
                                                      const float* __restrict__ bq,
                                                      const float* __restrict__ Wkv,
                                                      const float* __restrict__ bkv) {
    extern __shared__ float ps[];
    const int tid = threadIdx.x;
    const int w = tid >> 5;
    const int lane = tid & 31;
    const int r0 = lane >> 2;
    const int q4 = lane & 3;
    const int m0 = blockIdx.x * 128;

    const int yb = blockIdx.y;
    const bool isQ = (yb < 12);
    const float* __restrict__ X = isQ ? X2 : X1;
    const float* __restrict__ W = isQ ? Wq : Wkv;
    const float* __restrict__ bias = isQ ? bq : bkv;
    const int n0 = isQ ? (yb * 64) : ((yb - 12) * 64);
    const bool is_v = (!isQ) && (n0 >= DMODEL);

    const uint32_t smem_u = s2u(ps);

    auto issue_chunk = [&](int kc, int buf) {
#pragma unroll
        for (int it = 0; it < 8; ++it) {
            int idx4 = tid + it * 128;
            int r = idx4 >> 3;
            int c4 = (idx4 & 7) * 4;
            CP_ASYNC16(smem_u + PX(buf, r, c4) * 4, &X[(m0 + r) * DMODEL + kc + c4]);
        }
#pragma unroll
        for (int it = 0; it < 4; ++it) {
            int idx4 = tid + it * 128;
            int r = idx4 >> 3;
            int c4 = (idx4 & 7) * 4;
            CP_ASYNC16(smem_u + PW(buf, r, c4) * 4, &W[(n0 + r) * DMODEL + kc + c4]);
        }
        CP_COMMIT();
    };

    issue_chunk(0, 0);

    float acc[2][8][4];
#pragma unroll
    for (int t = 0; t < 2; ++t)
#pragma unroll
        for (int i = 0; i < 8; ++i) {
            acc[t][i][0] = 0.f; acc[t][i][1] = 0.f; acc[t][i][2] = 0.f; acc[t][i][3] = 0.f;
        }

    int buf = 0;
    for (int kc = 0; kc < DMODEL; kc += 32) {
        CP_WAIT0();
        __syncthreads();
        if (kc + 32 < DMODEL) issue_chunk(kc + 32, buf ^ 1);

        if (!is_v) {
#pragma unroll
            for (int kk = 0; kk < 4; ++kk) {
                const int k0 = kk * 8 + q4;
                uint32_t ah[2][4], al[2][4];
#pragma unroll
                for (int t = 0; t < 2; ++t) {
                    const int rowA = w * 32 + t * 16 + r0;
                    float a0f = ps[PX(buf, rowA, k0)];
                    float a1f = ps[PX(buf, rowA + 8, k0)];
                    float a2f = ps[PX(buf, rowA, k0 + 4)];
                    float a3f = ps[PX(buf, rowA + 8, k0 + 4)];
                    float h0 = trunc_hi(a0f), h1 = trunc_hi(a1f), h2 = trunc_hi(a2f), h3 = trunc_hi(a3f);
                    ah[t][0] = __float_as_uint(h0); al[t][0] = __float_as_uint(a0f - h0);
                    ah[t][1] = __float_as_uint(h1); al[t][1] = __float_as_uint(a1f - h1);
                    ah[t][2] = __float_as_uint(h2); al[t][2] = __float_as_uint(a2f - h2);
                    ah[t][3] = __float_as_uint(h3); al[t][3] = __float_as_uint(a3f - h3);
                }
#pragma unroll
                for (int nt = 0; nt < 8; ++nt) {
                    float b0f = ps[PW(buf, nt * 8 + r0, k0)];
                    float b1f = ps[PW(buf, nt * 8 + r0, k0 + 4)];
                    float bh0f = trunc_hi(b0f), bh1f = trunc_hi(b1f);
                    uint32_t bh0 = __float_as_uint(bh0f), bh1 = __float_as_uint(bh1f);
                    uint32_t bl0 = __float_as_uint(b0f - bh0f), bl1 = __float_as_uint(b1f - bh1f);
#pragma unroll
                    for (int t = 0; t < 2; ++t) {
                        mma8(acc[t][nt], al[t][0], al[t][1], al[t][2], al[t][3], bh0, bh1);
                        mma8(acc[t][nt], ah[t][0], ah[t][1], ah[t][2], ah[t][3], bl0, bl1);
                        mma8(acc[t][nt], ah[t][0], ah[t][1], ah[t][2], ah[t][3], bh0, bh1);
                    }
                }
            }
        } else {
#pragma unroll
            for (int kk = 0; kk < 4; ++kk) {
                const int k0 = kk * 8 + q4;
                uint32_t ah[2][4];
#pragma unroll
                for (int t = 0; t < 2; ++t) {
                    const int rowA = w * 32 + t * 16 + r0;
                    ah[t][0] = f2tf(ps[PX(buf, rowA, k0)]);
                    ah[t][1] = f2tf(ps[PX(buf, rowA + 8, k0)]);
                    ah[t][2] = f2tf(ps[PX(buf, rowA, k0 + 4)]);
                    ah[t][3] = f2tf(ps[PX(buf, rowA + 8, k0 + 4)]);
                }
#pragma unroll
                for (int nt = 0; nt < 8; ++nt) {
                    uint32_t bh0 = f2tf(ps[PW(buf, nt * 8 + r0, k0)]);
                    uint32_t bh1 = f2tf(ps[PW(buf, nt * 8 + r0, k0 + 4)]);
#pragma unroll
                    for (int t = 0; t < 2; ++t)
                        mma8(acc[t][nt], ah[t][0], ah[t][1], ah[t][2], ah[t][3], bh0, bh1);
                }
            }
        }
        buf ^= 1;
    }

    const int c0 = q4 * 2;
#pragma unroll
    for (int nt = 0; nt < 8; ++nt) {
        int n = n0 + nt * 8 + c0;
        float bias0 = bias[n];
        float bias1 = bias[n + 1];
        float* dst;
        int nn = n;
        if (isQ) {
            dst = g_Q;
        } else if (n < DMODEL) {
            dst = g_K;
        } else {
            dst = g_V;
            nn = n - DMODEL;
        }
        int hh = nn >> 6;
        int dd = nn & 63;
#pragma unroll
        for (int t = 0; t < 2; ++t)
#pragma unroll
            for (int half = 0; half < 2; ++half) {
                int m = m0 + w * 32 + t * 16 + r0 + half * 8;
                int btk = m >> 11;
                int itok = m & (NTOK - 1);
                float v0 = acc[t][nt][half * 2 + 0] + bias0;
                float v1 = acc[t][nt][half * 2 + 1] + bias1;
                int idx = ((btk * HNUM + hh) * NTOK + itok) << 6;
                if (is_v) {
                    // V: pre-round to tf32 (bit-identical to rounding at attn PV load)
                    *reinterpret_cast<float2*>(&dst[idx + dd]) =
                        make_float2(__uint_as_float(f2tf(v0)), __uint_as_float(f2tf(v1)));
                } else {
                    *reinterpret_cast<float2*>(&dst[idx + dd]) = make_float2(v0, v1);
                }
            }
    }
}

// ===================== flash attention: R11 core (split-K=2) + preround-V PV =============
#define SSTRIDE 68
#define QROWS 128
#define KVBUF (64 * SSTRIDE)
__global__ __launch_bounds__(128, 2) void attn_kernel() {
    extern __shared__ float sm[];
    float* Qs = sm;  // 128 x 68 fp32 (scaled by log2e)

    const int tid = threadIdx.x;
    const int w = tid >> 5;
    const int lane = tid & 31;
    const int r0 = lane >> 2;
    const int q4 = lane & 3;
    const int zz = blockIdx.z;
    const int b = zz >> 1;
    const int kvhalf = zz & 1;
    const int h = blockIdx.y;
    const int i0 = blockIdx.x * QROWS;
    const int jbase = kvhalf * (NTOK / 2);

    const int base = ((b * HNUM + h) * NTOK) * PD;
    const float* __restrict__ Qg = g_Q + base;
    const float* __restrict__ Kg = g_K + base;
    const float* __restrict__ Vg = g_V + base;
    float* __restrict__ Og = g_Opart + kvhalf * ODSZ + base;
    float* __restrict__ Lg = g_lpart + kvhalf * LSZ + (b * HNUM + h) * NTOK;

    const uint32_t kv_u = s2u(sm) + QROWS * SSTRIDE * 4;

    auto issue_chunk = [&](int j0, int buf) {
        uint32_t kb = kv_u + (uint32_t)buf * (2 * KVBUF * 4);
#pragma unroll
        for (int it = 0; it < 8; ++it) {
            int idx4 = tid + it * 128;
            int r = idx4 >> 4;
            int c4 = (idx4 & 15) * 4;
            uint32_t so = (uint32_t)(r * SSTRIDE + c4) * 4;
            CP_ASYNC16(kb + so, &Kg[(j0 + r) * PD + c4]);
            // V rows permuted within each 8-block: smem row k holds key (k<4 ? 2k : 2k-7)
            int k = r & 7;
            int pr = (r & ~7) | ((k < 4) ? (k << 1) : ((k << 1) - 7));
            CP_ASYNC16(kb + KVBUF * 4 + so, &Vg[(j0 + pr) * PD + c4]);
        }
        CP_COMMIT();
    };

    issue_chunk(jbase, 0);

    const float LOG2E = 1.4426950408889634f;
    // stage Q tile (128 x 64), scaled by log2e
#pragma unroll
    for (int it = 0; it < 16; ++it) {
        int idx4 = tid + it * 128;
        int r = idx4 >> 4;
        int c4 = (idx4 & 15) * 4;
        float4 qv = *reinterpret_cast<const float4*>(&Qg[(i0 + r) * PD + c4]);
        *reinterpret_cast<float4*>(&Qs[r * SSTRIDE + c4]) =
            make_float4(qv.x * LOG2E, qv.y * LOG2E, qv.z * LOG2E, qv.w * LOG2E);
    }

    float lr[4] = {0.f, 0.f, 0.f, 0.f};
    float Oacc[2][8][4];
#pragma unroll
    for (int t = 0; t < 2; ++t)
#pragma unroll
        for (int i = 0; i < 8; ++i) {
            Oacc[t][i][0] = 0.f; Oacc[t][i][1] = 0.f; Oacc[t][i][2] = 0.f; Oacc[t][i][3] = 0.f;
        }

    int buf = 0;
    for (int j0 = jbase; j0 < jbase + NTOK / 2; j0 += 64) {
        CP_WAIT0();
        __syncthreads();
        if (j0 + 64 < jbase + NTOK / 2) issue_chunk(j0 + 64, buf ^ 1);

        const float* Ks = sm + QROWS * SSTRIDE + buf * 2 * KVBUF;
        const float* Vs = Ks + KVBUF;

        // ---- S' = (log2e * Q) K^T : exact-split 3xTF32 ----
        float s[2][8][4];
#pragma unroll
        for (int t = 0; t < 2; ++t)
#pragma unroll
            for (int i = 0; i < 8; ++i) {
                s[t][i][0] = 0.f; s[t][i][1] = 0.f; s[t][i][2] = 0.f; s[t][i][3] = 0.f;
            }
#pragma unroll
        for (int kk = 0; kk < 8; ++kk) {
            const int k0 = kk * 8 + q4;
            uint32_t ah[2][4], al[2][4];
#pragma unroll
            for (int t = 0; t < 2; ++t) {
                const int rowA = w * 32 + t * 16 + r0;
                float a0f = Qs[rowA * SSTRIDE + k0];
                float a1f = Qs[(rowA + 8) * SSTRIDE + k0];
                float a2f = Qs[rowA * SSTRIDE + k0 + 4];
                float a3f = Qs[(rowA + 8) * SSTRIDE + k0 + 4];
                float h0 = trunc_hi(a0f), h1 = trunc_hi(a1f), h2 = trunc_hi(a2f), h3 = trunc_hi(a3f);
                ah[t][0] = __float_as_uint(h0); al[t][0] = __float_as_uint(a0f - h0);
                ah[t][1] = __float_as_uint(h1); al[t][1] = __float_as_uint(a1f - h1);
                ah[t][2] = __float_as_uint(h2); al[t][2] = __float_as_uint(a2f - h2);
                ah[t][3] = __float_as_uint(h3); al[t][3] = __float_as_uint(a3f - h3);
            }
#pragma unroll
            for (int nt = 0; nt < 8; ++nt) {
                float b0f = Ks[(nt * 8 + r0) * SSTRIDE + k0];
                float b1f = Ks[(nt * 8 + r0) * SSTRIDE + k0 + 4];
                float bh0f = trunc_hi(b0f), bh1f = trunc_hi(b1f);
                uint32_t bh0 = __float_as_uint(bh0f), bh1 = __float_as_uint(bh1f);
                uint32_t bl0 = __float_as_uint(b0f - bh0f), bl1 = __float_as_uint(b1f - bh1f);
#pragma unroll
                for (int t = 0; t < 2; ++t) {
                    mma8(s[t][nt], al[t][0], al[t][1], al[t][2], al[t][3], bh0, bh1);
                    mma8(s[t][nt], ah[t][0], ah[t][1], ah[t][2], ah[t][3], bl0, bl1);
                    mma8(s[t][nt], ah[t][0], ah[t][1], ah[t][2], ah[t][3], bh0, bh1);
                }
            }
        }

        // ---- p = 2^(S'); accumulate row sums; P -> tf32 in registers ----
#pragma unroll
        for (int t = 0; t < 2; ++t) {
            float ps0 = 0.f, ps1 = 0.f;
#pragma unroll
            for (int nt = 0; nt < 8; ++nt) {
                float p0 = ex2f(s[t][nt][0]);
                float p1 = ex2f(s[t][nt][1]);
                float p2 = ex2f(s[t][nt][2]);
                float p3 = ex2f(s[t][nt][3]);
                ps0 += p0 + p1;
                ps1 += p2 + p3;
                s[t][nt][0] = __uint_as_float(f2tf(p0));
                s[t][nt][1] = __uint_as_float(f2tf(p1));
                s[t][nt][2] = __uint_as_float(f2tf(p2));
                s[t][nt][3] = __uint_as_float(f2tf(p3));
            }
            ps0 += __shfl_xor_sync(0xffffffffu, ps0, 1);
            ps0 += __shfl_xor_sync(0xffffffffu, ps0, 2);
            ps1 += __shfl_xor_sync(0xffffffffu, ps1, 1);
            ps1 += __shfl_xor_sync(0xffffffffu, ps1, 2);
            lr[2 * t] += ps0;
            lr[2 * t + 1] += ps1;
        }

        // ---- O += P V : A-frag IS the C-frag (V rows pre-permuted); V already tf32 ----
#pragma unroll
        for (int kk = 0; kk < 8; ++kk) {
#pragma unroll
            for (int dt = 0; dt < 8; ++dt) {
                uint32_t b0 = __float_as_uint(Vs[(kk * 8 + q4) * SSTRIDE + dt * 8 + r0]);
                uint32_t b1 = __float_as_uint(Vs[(kk * 8 + q4 + 4) * SSTRIDE + dt * 8 + r0]);
#pragma unroll
                for (int t = 0; t < 2; ++t)
                    mma8(Oacc[t][dt],
                         __float_as_uint(s[t][kk][0]), __float_as_uint(s[t][kk][2]),
                         __float_as_uint(s[t][kk][1]), __float_as_uint(s[t][kk][3]),
                         b0, b1);
            }
        }
        buf ^= 1;
    }

    // ---- epilogue: write unnormalized O and row sums l ----
#pragma unroll
    for (int t = 0; t < 2; ++t) {
        const int orow = i0 + w * 32 + t * 16 + r0;
        if (q4 == 0) {
            Lg[orow] = lr[2 * t];
            Lg[orow + 8] = lr[2 * t + 1];
        }
#pragma unroll
        for (int dt = 0; dt < 8; ++dt) {
            *reinterpret_cast<float2*>(&Og[orow * PD + dt * 8 + 2 * q4]) =
                make_float2(Oacc[t][dt][0], Oacc[t][dt][1]);
            *reinterpret_cast<float2*>(&Og[(orow + 8) * PD + dt * 8 + 2 * q4]) =
                make_float2(Oacc[t][dt][2], Oacc[t][dt][3]);
        }
    }
}

// ===================== combine: out = (O0 + O1) / (l0 + l1) ==============================
__global__ __launch_bounds__(256) void combine_kernel(float* __restrict__ out) {
    int idx4 = blockIdx.x * 256 + threadIdx.x;
    int fidx = idx4 * 4;
    int rowg = fidx >> 6;  // PD = 64
    float inv = 1.0f / (g_lpart[rowg] + g_lpart[LSZ + rowg]);
    float4 a = *reinterpret_cast<const float4*>(&g_Opart[fidx]);
    float4 c = *reinterpret_cast<const float4*>(&g_Opart[ODSZ + fidx]);
    *reinterpret_cast<float4*>(&out[fidx]) =
        make_float4((a.x + c.x) * inv, (a.y + c.y) * inv, (a.z + c.z) * inv, (a.w + c.w) * inv);
}

extern "C" void kernel_launch(void* const* d_in, const int* in_sizes, int n_in,
                              void* d_out, int out_size) {
    (void)in_sizes; (void)n_in; (void)out_size;
    const float* x1 = (const float*)d_in[0];
    const float* x2 = (const float*)d_in[1];
    const float* Wq = (const float*)d_in[2];
    const float* bq = (const float*)d_in[3];
    const float* Wkv = (const float*)d_in[4];
    const float* bkv = (const float*)d_in[5];
    float* out = (float*)d_out;

    const int proj_smem = PROJ_SMEM_FLOATS * sizeof(float);  // 55296
    cudaFuncSetAttribute(proj_kernel, cudaFuncAttributeMaxDynamicSharedMemorySize, proj_smem);
    cudaFuncSetAttribute(proj_kernel, cudaFuncAttributePreferredSharedMemoryCarveout, 100);
    proj_kernel<<<dim3(32, 36), 128, proj_smem>>>(x2, x1, Wq, bq, Wkv, bkv);

    const int smem_bytes = (QROWS * SSTRIDE + 4 * KVBUF) * sizeof(float);  // 104448
    cudaFuncSetAttribute(attn_kernel, cudaFuncAttributeMaxDynamicSharedMemorySize, smem_bytes);
    cudaFuncSetAttribute(attn_kernel, cudaFuncAttributePreferredSharedMemoryCarveout, 100);
    attn_kernel<<<dim3(NTOK / QROWS, HNUM, BATCH * 2), 128, smem_bytes>>>();

    combine_kernel<<<ODSZ / 4 / 256, 256>>>(out);
}

// round 15
// speedup vs baseline: 1.1070x; 1.0167x over previous
#include <cuda_runtime.h>
#include <cstdint>

#define HNUM 12
#define NTOK 2048
#define DMODEL 768
#define PD 64
#define BATCH 2
#define ODSZ (BATCH * HNUM * NTOK * PD)
#define LSZ (BATCH * HNUM * NTOK)

// scratch (device globals — no allocations allowed)
static __device__ float g_Q[ODSZ];
static __device__ float g_K[ODSZ];
static __device__ float g_V[ODSZ];   // pre-rounded to tf32 at proj store
static __device__ float g_Opart[2 * ODSZ];  // unnormalized O per KV-half
static __device__ float g_lpart[2 * LSZ];   // row sums per KV-half

__device__ __forceinline__ uint32_t f2tf(float x) {
    uint32_t u;
    asm("cvt.rna.tf32.f32 %0, %1;" : "=r"(u) : "f"(x));
    return u;
}
// exact split: hi = x with low 13 mantissa bits cleared (valid tf32), lo = x - hi (exact)
__device__ __forceinline__ float trunc_hi(float x) {
    return __uint_as_float(__float_as_uint(x) & 0xFFFFE000u);
}
__device__ __forceinline__ float ex2f(float x) {
    float r;
    asm("ex2.approx.f32 %0, %1;" : "=f"(r) : "f"(x));
    return r;
}

__device__ __forceinline__ void mma8(float c[4], uint32_t a0, uint32_t a1, uint32_t a2, uint32_t a3,
                                     uint32_t b0, uint32_t b1) {
    asm volatile(
        "mma.sync.aligned.m16n8k8.row.col.f32.tf32.tf32.f32 "
        "{%0,%1,%2,%3},{%4,%5,%6,%7},{%8,%9},{%0,%1,%2,%3};\n"
        : "+f"(c[0]), "+f"(c[1]), "+f"(c[2]), "+f"(c[3])
        : "r"(a0), "r"(a1), "r"(a2), "r"(a3), "r"(b0), "r"(b1));
}

__device__ __forceinline__ uint32_t s2u(const void* p) {
    uint32_t a;
    asm("{ .reg .u64 t; cvta.to.shared.u64 t, %1; cvt.u32.u64 %0, t; }" : "=r"(a) : "l"(p));
    return a;
}
#define CP_ASYNC16(sa, ga) \
    asm volatile("cp.async.cg.shared.global [%0], [%1], 16;" :: "r"(sa), "l"(ga) : "memory")
#define CP_COMMIT() asm volatile("cp.async.commit_group;" ::: "memory")
#define CP_WAIT0() asm volatile("cp.async.wait_group 0;" ::: "memory")

// ===================== projection: cp.async double-buffer, 4 CTAs/SM (frozen R14) ========
#define PX(buf, r, c) ((buf) * 4608 + (r) * 36 + (c))
#define PW(buf, r, c) (9216 + (buf) * 2304 + (r) * 36 + (c))
#define PROJ_SMEM_FLOATS (9216 + 4608)
__global__ __launch_bounds__(128, 4) void proj_kernel(const float* __restrict__ X2,
                                                      const float* __restrict__ X1,
                                                      const float* __restrict__ Wq,
                                                      const float* __restrict__ bq,
                                                      const float* __restrict__ Wkv,
                                                      const float* __restrict__ bkv) {
    extern __shared__ float ps[];
    const int tid = threadIdx.x;
    const int w = tid >> 5;
    const int lane = tid & 31;
    const int r0 = lane >> 2;
    const int q4 = lane & 3;
    const int m0 = blockIdx.x * 128;

    const int yb = blockIdx.y;
    const bool isQ = (yb < 12);
    const float* __restrict__ X = isQ ? X2 : X1;
    const float* __restrict__ W = isQ ? Wq : Wkv;
    const float* __restrict__ bias = isQ ? bq : bkv;
    const int n0 = isQ ? (yb * 64) : ((yb - 12) * 64);
    const bool is_v = (!isQ) && (n0 >= DMODEL);

    const uint32_t smem_u = s2u(ps);

    auto issue_chunk = [&](int kc, int buf) {
#pragma unroll
        for (int it = 0; it < 8; ++it) {
            int idx4 = tid + it * 128;
            int r = idx4 >> 3;
            int c4 = (idx4 & 7) * 4;
            CP_ASYNC16(smem_u + PX(buf, r, c4) * 4, &X[(m0 + r) * DMODEL + kc + c4]);
        }
#pragma unroll
        for (int it = 0; it < 4; ++it) {
            int idx4 = tid + it * 128;
            int r = idx4 >> 3;
            int c4 = (idx4 & 7) * 4;
            CP_ASYNC16(smem_u + PW(buf, r, c4) * 4, &W[(n0 + r) * DMODEL + kc + c4]);
        }
        CP_COMMIT();
    };

    issue_chunk(0, 0);

    float acc[2][8][4];
#pragma unroll
    for (int t = 0; t < 2; ++t)
#pragma unroll
        for (int i = 0; i < 8; ++i) {
            acc[t][i][0] = 0.f; acc[t][i][1] = 0.f; acc[t][i][2] = 0.f; acc[t][i][3] = 0.f;
        }

    int buf = 0;
    for (int kc = 0; kc < DMODEL; kc += 32) {
        CP_WAIT0();
        __syncthreads();
        if (kc + 32 < DMODEL) issue_chunk(kc + 32, buf ^ 1);

        if (!is_v) {
#pragma unroll
            for (int kk = 0; kk < 4; ++kk) {
                const int k0 = kk * 8 + q4;
                uint32_t ah[2][4], al[2][4];
#pragma unroll
                for (int t = 0; t < 2; ++t) {
                    const int rowA = w * 32 + t * 16 + r0;
                    float a0f = ps[PX(buf, rowA, k0)];
                    float a1f = ps[PX(buf, rowA + 8, k0)];
                    float a2f = ps[PX(buf, rowA, k0 + 4)];
                    float a3f = ps[PX(buf, rowA + 8, k0 + 4)];
                    float h0 = trunc_hi(a0f), h1 = trunc_hi(a1f), h2 = trunc_hi(a2f), h3 = trunc_hi(a3f);
                    ah[t][0] = __float_as_uint(h0); al[t][0] = __float_as_uint(a0f - h0);
                    ah[t][1] = __float_as_uint(h1); al[t][1] = __float_as_uint(a1f - h1);
                    ah[t][2] = __float_as_uint(h2); al[t][2] = __float_as_uint(a2f - h2);
                    ah[t][3] = __float_as_uint(h3); al[t][3] = __float_as_uint(a3f - h3);
                }
#pragma unroll
                for (int nt = 0; nt < 8; ++nt) {
                    float b0f = ps[PW(buf, nt * 8 + r0, k0)];
                    float b1f = ps[PW(buf, nt * 8 + r0, k0 + 4)];
                    float bh0f = trunc_hi(b0f), bh1f = trunc_hi(b1f);
                    uint32_t bh0 = __float_as_uint(bh0f), bh1 = __float_as_uint(bh1f);
                    uint32_t bl0 = __float_as_uint(b0f - bh0f), bl1 = __float_as_uint(b1f - bh1f);
#pragma unroll
                    for (int t = 0; t < 2; ++t) {
                        mma8(acc[t][nt], al[t][0], al[t][1], al[t][2], al[t][3], bh0, bh1);
                        mma8(acc[t][nt], ah[t][0], ah[t][1], ah[t][2], ah[t][3], bl0, bl1);
                        mma8(acc[t][nt], ah[t][0], ah[t][1], ah[t][2], ah[t][3], bh0, bh1);
                    }
                }
            }
        } else {
#pragma unroll
            for (int kk = 0; kk < 4; ++kk) {
                const int k0 = kk * 8 + q4;
                uint32_t ah[2][4];
#pragma unroll
                for (int t = 0; t < 2; ++t) {
                    const int rowA = w * 32 + t * 16 + r0;
                    ah[t][0] = f2tf(ps[PX(buf, rowA, k0)]);
                    ah[t][1] = f2tf(ps[PX(buf, rowA + 8, k0)]);
                    ah[t][2] = f2tf(ps[PX(buf, rowA, k0 + 4)]);
                    ah[t][3] = f2tf(ps[PX(buf, rowA + 8, k0 + 4)]);
                }
#pragma unroll
                for (int nt = 0; nt < 8; ++nt) {
                    uint32_t bh0 = f2tf(ps[PW(buf, nt * 8 + r0, k0)]);
                    uint32_t bh1 = f2tf(ps[PW(buf, nt * 8 + r0, k0 + 4)]);
#pragma unroll
                    for (int t = 0; t < 2; ++t)
                        mma8(acc[t][nt], ah[t][0], ah[t][1], ah[t][2], ah[t][3], bh0, bh1);
                }
            }
        }
        buf ^= 1;
    }

    const int c0 = q4 * 2;
#pragma unroll
    for (int nt = 0; nt < 8; ++nt) {
        int n = n0 + nt * 8 + c0;
        float bias0 = bias[n];
        float bias1 = bias[n + 1];
        float* dst;
        int nn = n;
        if (isQ) {
            dst = g_Q;
        } else if (n < DMODEL) {
            dst = g_K;
        } else {
            dst = g_V;
            nn = n - DMODEL;
        }
        int hh = nn >> 6;
        int dd = nn & 63;
#pragma unroll
        for (int t = 0; t < 2; ++t)
#pragma unroll
            for (int half = 0; half < 2; ++half) {
                int m = m0 + w * 32 + t * 16 + r0 + half * 8;
                int btk = m >> 11;
                int itok = m & (NTOK - 1);
                float v0 = acc[t][nt][half * 2 + 0] + bias0;
                float v1 = acc[t][nt][half * 2 + 1] + bias1;
                int idx = ((btk * HNUM + hh) * NTOK + itok) << 6;
                if (is_v) {
                    // V: pre-round to tf32 (bit-identical to rounding at attn PV load)
                    *reinterpret_cast<float2*>(&dst[idx + dd]) =
                        make_float2(__uint_as_float(f2tf(v0)), __uint_as_float(f2tf(v1)));
                } else {
                    *reinterpret_cast<float2*>(&dst[idx + dd]) = make_float2(v0, v1);
                }
            }
    }
}

// ===================== flash attention: split-K=2, raw-P PV, deferred l-reduction ========
#define SSTRIDE 68
#define QROWS 128
#define KVBUF (64 * SSTRIDE)
__global__ __launch_bounds__(128, 2) void attn_kernel() {
    extern __shared__ float sm[];
    float* Qs = sm;  // 128 x 68 fp32 (scaled by log2e)

    const int tid = threadIdx.x;
    const int w = tid >> 5;
    const int lane = tid & 31;
    const int r0 = lane >> 2;
    const int q4 = lane & 3;
    const int zz = blockIdx.z;
    const int b = zz >> 1;
    const int kvhalf = zz & 1;
    const int h = blockIdx.y;
    const int i0 = blockIdx.x * QROWS;
    const int jbase = kvhalf * (NTOK / 2);

    const int base = ((b * HNUM + h) * NTOK) * PD;
    const float* __restrict__ Qg = g_Q + base;
    const float* __restrict__ Kg = g_K + base;
    const float* __restrict__ Vg = g_V + base;
    float* __restrict__ Og = g_Opart + kvhalf * ODSZ + base;
    float* __restrict__ Lg = g_lpart + kvhalf * LSZ + (b * HNUM + h) * NTOK;

    const uint32_t kv_u = s2u(sm) + QROWS * SSTRIDE * 4;

    auto issue_chunk = [&](int j0, int buf) {
        uint32_t kb = kv_u + (uint32_t)buf * (2 * KVBUF * 4);
#pragma unroll
        for (int it = 0; it < 8; ++it) {
            int idx4 = tid + it * 128;
            int r = idx4 >> 4;
            int c4 = (idx4 & 15) * 4;
            uint32_t so = (uint32_t)(r * SSTRIDE + c4) * 4;
            CP_ASYNC16(kb + so, &Kg[(j0 + r) * PD + c4]);
            // V rows permuted within each 8-block: smem row k holds key (k<4 ? 2k : 2k-7)
            int k = r & 7;
            int pr = (r & ~7) | ((k < 4) ? (k << 1) : ((k << 1) - 7));
            CP_ASYNC16(kb + KVBUF * 4 + so, &Vg[(j0 + pr) * PD + c4]);
        }
        CP_COMMIT();
    };

    issue_chunk(jbase, 0);

    const float LOG2E = 1.4426950408889634f;
    // stage Q tile (128 x 64), scaled by log2e
#pragma unroll
    for (int it = 0; it < 16; ++it) {
        int idx4 = tid + it * 128;
        int r = idx4 >> 4;
        int c4 = (idx4 & 15) * 4;
        float4 qv = *reinterpret_cast<const float4*>(&Qg[(i0 + r) * PD + c4]);
        *reinterpret_cast<float4*>(&Qs[r * SSTRIDE + c4]) =
            make_float4(qv.x * LOG2E, qv.y * LOG2E, qv.z * LOG2E, qv.w * LOG2E);
    }

    float lr[4] = {0.f, 0.f, 0.f, 0.f};  // per-lane partial row sums (reduced in epilogue)
    float Oacc[2][8][4];
#pragma unroll
    for (int t = 0; t < 2; ++t)
#pragma unroll
        for (int i = 0; i < 8; ++i) {
            Oacc[t][i][0] = 0.f; Oacc[t][i][1] = 0.f; Oacc[t][i][2] = 0.f; Oacc[t][i][3] = 0.f;
        }

    int buf = 0;
    for (int j0 = jbase; j0 < jbase + NTOK / 2; j0 += 64) {
        CP_WAIT0();
        __syncthreads();
        if (j0 + 64 < jbase + NTOK / 2) issue_chunk(j0 + 64, buf ^ 1);

        const float* Ks = sm + QROWS * SSTRIDE + buf * 2 * KVBUF;
        const float* Vs = Ks + KVBUF;

        // ---- S' = (log2e * Q) K^T : exact-split 3xTF32 ----
        float s[2][8][4];
#pragma unroll
        for (int t = 0; t < 2; ++t)
#pragma unroll
            for (int i = 0; i < 8; ++i) {
                s[t][i][0] = 0.f; s[t][i][1] = 0.f; s[t][i][2] = 0.f; s[t][i][3] = 0.f;
            }
#pragma unroll
        for (int kk = 0; kk < 8; ++kk) {
            const int k0 = kk * 8 + q4;
            uint32_t ah[2][4], al[2][4];
#pragma unroll
            for (int t = 0; t < 2; ++t) {
                const int rowA = w * 32 + t * 16 + r0;
                float a0f = Qs[rowA * SSTRIDE + k0];
                float a1f = Qs[(rowA + 8) * SSTRIDE + k0];
                float a2f = Qs[rowA * SSTRIDE + k0 + 4];
                float a3f = Qs[(rowA + 8) * SSTRIDE + k0 + 4];
                float h0 = trunc_hi(a0f), h1 = trunc_hi(a1f), h2 = trunc_hi(a2f), h3 = trunc_hi(a3f);
                ah[t][0] = __float_as_uint(h0); al[t][0] = __float_as_uint(a0f - h0);
                ah[t][1] = __float_as_uint(h1); al[t][1] = __float_as_uint(a1f - h1);
                ah[t][2] = __float_as_uint(h2); al[t][2] = __float_as_uint(a2f - h2);
                ah[t][3] = __float_as_uint(h3); al[t][3] = __float_as_uint(a3f - h3);
            }
#pragma unroll
            for (int nt = 0; nt < 8; ++nt) {
                float b0f = Ks[(nt * 8 + r0) * SSTRIDE + k0];
                float b1f = Ks[(nt * 8 + r0) * SSTRIDE + k0 + 4];
                float bh0f = trunc_hi(b0f), bh1f = trunc_hi(b1f);
                uint32_t bh0 = __float_as_uint(bh0f), bh1 = __float_as_uint(bh1f);
                uint32_t bl0 = __float_as_uint(b0f - bh0f), bl1 = __float_as_uint(b1f - bh1f);
#pragma unroll
                for (int t = 0; t < 2; ++t) {
                    mma8(s[t][nt], al[t][0], al[t][1], al[t][2], al[t][3], bh0, bh1);
                    mma8(s[t][nt], ah[t][0], ah[t][1], ah[t][2], ah[t][3], bl0, bl1);
                    mma8(s[t][nt], ah[t][0], ah[t][1], ah[t][2], ah[t][3], bh0, bh1);
                }
            }
        }

        // ---- p = 2^(S'); accumulate per-lane partial sums; P kept raw (HW converts) ----
#pragma unroll
        for (int t = 0; t < 2; ++t) {
            float ps0 = 0.f, ps1 = 0.f;
#pragma unroll
            for (int nt = 0; nt < 8; ++nt) {
                float p0 = ex2f(s[t][nt][0]);
                float p1 = ex2f(s[t][nt][1]);
                float p2 = ex2f(s[t][nt][2]);
                float p3 = ex2f(s[t][nt][3]);
                ps0 += p0 + p1;
                ps1 += p2 + p3;
                s[t][nt][0] = p0;
                s[t][nt][1] = p1;
                s[t][nt][2] = p2;
                s[t][nt][3] = p3;
            }
            lr[2 * t] += ps0;
            lr[2 * t + 1] += ps1;
        }

        // ---- O += P V : A-frag IS the C-frag (V rows pre-permuted); V already tf32 ----
#pragma unroll
        for (int kk = 0; kk < 8; ++kk) {
#pragma unroll
            for (int dt = 0; dt < 8; ++dt) {
                uint32_t b0 = __float_as_uint(Vs[(kk * 8 + q4) * SSTRIDE + dt * 8 + r0]);
                uint32_t b1 = __float_as_uint(Vs[(kk * 8 + q4 + 4) * SSTRIDE + dt * 8 + r0]);
#pragma unroll
                for (int t = 0; t < 2; ++t)
                    mma8(Oacc[t][dt],
                         __float_as_uint(s[t][kk][0]), __float_as_uint(s[t][kk][2]),
                         __float_as_uint(s[t][kk][1]), __float_as_uint(s[t][kk][3]),
                         b0, b1);
            }
        }
        buf ^= 1;
    }

    // ---- epilogue: quad-reduce row sums once, write unnormalized O and l ----
#pragma unroll
    for (int i = 0; i < 4; ++i) {
        lr[i] += __shfl_xor_sync(0xffffffffu, lr[i], 1);
        lr[i] += __shfl_xor_sync(0xffffffffu, lr[i], 2);
    }
#pragma unroll
    for (int t = 0; t < 2; ++t) {
        const int orow = i0 + w * 32 + t * 16 + r0;
        if (q4 == 0) {
            Lg[orow] = lr[2 * t];
            Lg[orow + 8] = lr[2 * t + 1];
        }
#pragma unroll
        for (int dt = 0; dt < 8; ++dt) {
            *reinterpret_cast<float2*>(&Og[orow * PD + dt * 8 + 2 * q4]) =
                make_float2(Oacc[t][dt][0], Oacc[t][dt][1]);
            *reinterpret_cast<float2*>(&Og[(orow + 8) * PD + dt * 8 + 2 * q4]) =
                make_float2(Oacc[t][dt][2], Oacc[t][dt][3]);
        }
    }
}

// ===================== combine: out = (O0 + O1) / (l0 + l1) ==============================
__global__ __launch_bounds__(256) void combine_kernel(float* __restrict__ out) {
    int idx4 = blockIdx.x * 256 + threadIdx.x;
    int fidx = idx4 * 4;
    int rowg = fidx >> 6;  // PD = 64
    float inv = 1.0f / (g_lpart[rowg] + g_lpart[LSZ + rowg]);
    float4 a = *reinterpret_cast<const float4*>(&g_Opart[fidx]);
    float4 c = *reinterpret_cast<const float4*>(&g_Opart[ODSZ + fidx]);
    *reinterpret_cast<float4*>(&out[fidx]) =
        make_float4((a.x + c.x) * inv, (a.y + c.y) * inv, (a.z + c.z) * inv, (a.w + c.w) * inv);
}

extern "C" void kernel_launch(void* const* d_in, const int* in_sizes, int n_in,
                              void* d_out, int out_size) {
    (void)in_sizes; (void)n_in; (void)out_size;
    const float* x1 = (const float*)d_in[0];
    const float* x2 = (const float*)d_in[1];
    const float* Wq = (const float*)d_in[2];
    const float* bq = (const float*)d_in[3];
    const float* Wkv = (const float*)d_in[4];
    const float* bkv = (const float*)d_in[5];
    float* out = (float*)d_out;

    const int proj_smem = PROJ_SMEM_FLOATS * sizeof(float);  // 55296
    cudaFuncSetAttribute(proj_kernel, cudaFuncAttributeMaxDynamicSharedMemorySize, proj_smem);
    cudaFuncSetAttribute(proj_kernel, cudaFuncAttributePreferredSharedMemoryCarveout, 100);
    proj_kernel<<<dim3(32, 36), 128, proj_smem>>>(x2, x1, Wq, bq, Wkv, bkv);

    const int smem_bytes = (QROWS * SSTRIDE + 4 * KVBUF) * sizeof(float);  // 104448
    cudaFuncSetAttribute(attn_kernel, cudaFuncAttributeMaxDynamicSharedMemorySize, smem_bytes);
    cudaFuncSetAttribute(attn_kernel, cudaFuncAttributePreferredSharedMemoryCarveout, 100);
    attn_kernel<<<dim3(NTOK / QROWS, HNUM, BATCH * 2), 128, smem_bytes>>>();

    combine_kernel<<<ODSZ / 4 / 256, 256>>>(out);
}

// round 16
// speedup vs baseline: 1.1614x; 1.0492x over previous
#include <cuda_runtime.h>
#include <cstdint>

#define HNUM 12
#define NTOK 2048
#define DMODEL 768
#define PD 64
#define BATCH 2
#define ODSZ (BATCH * HNUM * NTOK * PD)
#define LSZ (BATCH * HNUM * NTOK)
#define NSPLIT 3

// scratch (device globals — no allocations allowed)
static __device__ float g_Q[ODSZ];
static __device__ float g_K[ODSZ];
static __device__ float g_V[ODSZ];   // pre-rounded to tf32 at proj store
static __device__ float g_Opart[NSPLIT * ODSZ];  // unnormalized O per KV-part
static __device__ float g_lpart[NSPLIT * LSZ];   // row sums per KV-part

__device__ __forceinline__ uint32_t f2tf(float x) {
    uint32_t u;
    asm("cvt.rna.tf32.f32 %0, %1;" : "=r"(u) : "f"(x));
    return u;
}
// exact split: hi = x with low 13 mantissa bits cleared (valid tf32), lo = x - hi (exact)
__device__ __forceinline__ float trunc_hi(float x) {
    return __uint_as_float(__float_as_uint(x) & 0xFFFFE000u);
}
__device__ __forceinline__ float ex2f(float x) {
    float r;
    asm("ex2.approx.f32 %0, %1;" : "=f"(r) : "f"(x));
    return r;
}

__device__ __forceinline__ void mma8(float c[4], uint32_t a0, uint32_t a1, uint32_t a2, uint32_t a3,
                                     uint32_t b0, uint32_t b1) {
    asm volatile(
        "mma.sync.aligned.m16n8k8.row.col.f32.tf32.tf32.f32 "
        "{%0,%1,%2,%3},{%4,%5,%6,%7},{%8,%9},{%0,%1,%2,%3};\n"
        : "+f"(c[0]), "+f"(c[1]), "+f"(c[2]), "+f"(c[3])
        : "r"(a0), "r"(a1), "r"(a2), "r"(a3), "r"(b0), "r"(b1));
}

__device__ __forceinline__ uint32_t s2u(const void* p) {
    uint32_t a;
    asm("{ .reg .u64 t; cvta.to.shared.u64 t, %1; cvt.u32.u64 %0, t; }" : "=r"(a) : "l"(p));
    return a;
}
#define CP_ASYNC16(sa, ga) \
    asm volatile("cp.async.cg.shared.global [%0], [%1], 16;" :: "r"(sa), "l"(ga) : "memory")
#define CP_COMMIT() asm volatile("cp.async.commit_group;" ::: "memory")
#define CP_WAIT0() asm volatile("cp.async.wait_group 0;" ::: "memory")

// ===================== projection: cp.async double-buffer, 4 CTAs/SM (frozen R14) ========
#define PX(buf, r, c) ((buf) * 4608 + (r) * 36 + (c))
#define PW(buf, r, c) (9216 + (buf) * 2304 + (r) * 36 + (c))
#define PROJ_SMEM_FLOATS (9216 + 4608)
__global__ __launch_bounds__(128, 4) void proj_kernel(const float* __restrict__ X2,
                                                      const float* __restrict__ X1,
                                                      const float* __restrict__ Wq,
                                                      const float* __restrict__ bq,
                                                      const float* __restrict__ Wkv,
                                                      const float* __restrict__ bkv) {
    extern __shared__ float ps[];
    const int tid = threadIdx.x;
    const int w = tid >> 5;
    const int lane = tid & 31;
    const int r0 = lane >> 2;
    const int q4 = lane & 3;
    const int m0 = blockIdx.x * 128;

    const int yb = blockIdx.y;
    const bool isQ = (yb < 12);
    const float* __restrict__ X = isQ ? X2 : X1;
    const float* __restrict__ W = isQ ? Wq : Wkv;
    const float* __restrict__ bias = isQ ? bq : bkv;
    const int n0 = isQ ? (yb * 64) : ((yb - 12) * 64);
    const bool is_v = (!isQ) && (n0 >= DMODEL);

    const uint32_t smem_u = s2u(ps);

    auto issue_chunk = [&](int kc, int buf) {
#pragma unroll
        for (int it = 0; it < 8; ++it) {
            int idx4 = tid + it * 128;
            int r = idx4 >> 3;
            int c4 = (idx4 & 7) * 4;
            CP_ASYNC16(smem_u + PX(buf, r, c4) * 4, &X[(m0 + r) * DMODEL + kc + c4]);
        }
#pragma unroll
        for (int it = 0; it < 4; ++it) {
            int idx4 = tid + it * 128;
            int r = idx4 >> 3;
            int c4 = (idx4 & 7) * 4;
            CP_ASYNC16(smem_u + PW(buf, r, c4) * 4, &W[(n0 + r) * DMODEL + kc + c4]);
        }
        CP_COMMIT();
    };

    issue_chunk(0, 0);

    float acc[2][8][4];
#pragma unroll
    for (int t = 0; t < 2; ++t)
#pragma unroll
        for (int i = 0; i < 8; ++i) {
            acc[t][i][0] = 0.f; acc[t][i][1] = 0.f; acc[t][i][2] = 0.f; acc[t][i][3] = 0.f;
        }

    int buf = 0;
    for (int kc = 0; kc < DMODEL; kc += 32) {
        CP_WAIT0();
        __syncthreads();
        if (kc + 32 < DMODEL) issue_chunk(kc + 32, buf ^ 1);

        if (!is_v) {
#pragma unroll
            for (int kk = 0; kk < 4; ++kk) {
                const int k0 = kk * 8 + q4;
                uint32_t ah[2][4], al[2][4];
#pragma unroll
                for (int t = 0; t < 2; ++t) {
                    const int rowA = w * 32 + t * 16 + r0;
                    float a0f = ps[PX(buf, rowA, k0)];
                    float a1f = ps[PX(buf, rowA + 8, k0)];
                    float a2f = ps[PX(buf, rowA, k0 + 4)];
                    float a3f = ps[PX(buf, rowA + 8, k0 + 4)];
                    float h0 = trunc_hi(a0f), h1 = trunc_hi(a1f), h2 = trunc_hi(a2f), h3 = trunc_hi(a3f);
                    ah[t][0] = __float_as_uint(h0); al[t][0] = __float_as_uint(a0f - h0);
                    ah[t][1] = __float_as_uint(h1); al[t][1] = __float_as_uint(a1f - h1);
                    ah[t][2] = __float_as_uint(h2); al[t][2] = __float_as_uint(a2f - h2);
                    ah[t][3] = __float_as_uint(h3); al[t][3] = __float_as_uint(a3f - h3);
                }
#pragma unroll
                for (int nt = 0; nt < 8; ++nt) {
                    float b0f = ps[PW(buf, nt * 8 + r0, k0)];
                    float b1f = ps[PW(buf, nt * 8 + r0, k0 + 4)];
                    float bh0f = trunc_hi(b0f), bh1f = trunc_hi(b1f);
                    uint32_t bh0 = __float_as_uint(bh0f), bh1 = __float_as_uint(bh1f);
                    uint32_t bl0 = __float_as_uint(b0f - bh0f), bl1 = __float_as_uint(b1f - bh1f);
#pragma unroll
                    for (int t = 0; t < 2; ++t) {
                        mma8(acc[t][nt], al[t][0], al[t][1], al[t][2], al[t][3], bh0, bh1);
                        mma8(acc[t][nt], ah[t][0], ah[t][1], ah[t][2], ah[t][3], bl0, bl1);
                        mma8(acc[t][nt], ah[t][0], ah[t][1], ah[t][2], ah[t][3], bh0, bh1);
                    }
                }
            }
        } else {
#pragma unroll
            for (int kk = 0; kk < 4; ++kk) {
                const int k0 = kk * 8 + q4;
                uint32_t ah[2][4];
#pragma unroll
                for (int t = 0; t < 2; ++t) {
                    const int rowA = w * 32 + t * 16 + r0;
                    ah[t][0] = f2tf(ps[PX(buf, rowA, k0)]);
                    ah[t][1] = f2tf(ps[PX(buf, rowA + 8, k0)]);
                    ah[t][2] = f2tf(ps[PX(buf, rowA, k0 + 4)]);
                    ah[t][3] = f2tf(ps[PX(buf, rowA + 8, k0 + 4)]);
                }
#pragma unroll
                for (int nt = 0; nt < 8; ++nt) {
                    uint32_t bh0 = f2tf(ps[PW(buf, nt * 8 + r0, k0)]);
                    uint32_t bh1 = f2tf(ps[PW(buf, nt * 8 + r0, k0 + 4)]);
#pragma unroll
                    for (int t = 0; t < 2; ++t)
                        mma8(acc[t][nt], ah[t][0], ah[t][1], ah[t][2], ah[t][3], bh0, bh1);
                }
            }
        }
        buf ^= 1;
    }

    const int c0 = q4 * 2;
#pragma unroll
    for (int nt = 0; nt < 8; ++nt) {
        int n = n0 + nt * 8 + c0;
        float bias0 = bias[n];
        float bias1 = bias[n + 1];
        float* dst;
        int nn = n;
        if (isQ) {
            dst = g_Q;
        } else if (n < DMODEL) {
            dst = g_K;
        } else {
            dst = g_V;
            nn = n - DMODEL;
        }
        int hh = nn >> 6;
        int dd = nn & 63;
#pragma unroll
        for (int t = 0; t < 2; ++t)
#pragma unroll
            for (int half = 0; half < 2; ++half) {
                int m = m0 + w * 32 + t * 16 + r0 + half * 8;
                int btk = m >> 11;
                int itok = m & (NTOK - 1);
                float v0 = acc[t][nt][half * 2 + 0] + bias0;
                float v1 = acc[t][nt][half * 2 + 1] + bias1;
                int idx = ((btk * HNUM + hh) * NTOK + itok) << 6;
                if (is_v) {
                    // V: pre-round to tf32 (bit-identical to rounding at attn PV load)
                    *reinterpret_cast<float2*>(&dst[idx + dd]) =
                        make_float2(__uint_as_float(f2tf(v0)), __uint_as_float(f2tf(v1)));
                } else {
                    *reinterpret_cast<float2*>(&dst[idx + dd]) = make_float2(v0, v1);
                }
            }
    }
}

// ===================== flash attention: split-K=3 (chunks 11/11/10), raw-P PV ============
#define SSTRIDE 68
#define QROWS 128
#define KVBUF (64 * SSTRIDE)
__global__ __launch_bounds__(128, 2) void attn_kernel() {
    extern __shared__ float sm[];
    float* Qs = sm;  // 128 x 68 fp32 (scaled by log2e)

    const int tid = threadIdx.x;
    const int w = tid >> 5;
    const int lane = tid & 31;
    const int r0 = lane >> 2;
    const int q4 = lane & 3;
    const int zz = blockIdx.z;
    const int b = zz / NSPLIT;
    const int part = zz - b * NSPLIT;
    const int h = blockIdx.y;
    const int i0 = blockIdx.x * QROWS;
    // chunk ranges per part: [0,11), [11,22), [22,32)  (x64 keys)
    const int jbase = part * 11 * 64;
    const int jend = (part == 2) ? NTOK : (jbase + 11 * 64);

    const int base = ((b * HNUM + h) * NTOK) * PD;
    const float* __restrict__ Qg = g_Q + base;
    const float* __restrict__ Kg = g_K + base;
    const float* __restrict__ Vg = g_V + base;
    float* __restrict__ Og = g_Opart + part * ODSZ + base;
    float* __restrict__ Lg = g_lpart + part * LSZ + (b * HNUM + h) * NTOK;

    const uint32_t kv_u = s2u(sm) + QROWS * SSTRIDE * 4;

    auto issue_chunk = [&](int j0, int buf) {
        uint32_t kb = kv_u + (uint32_t)buf * (2 * KVBUF * 4);
#pragma unroll
        for (int it = 0; it < 8; ++it) {
            int idx4 = tid + it * 128;
            int r = idx4 >> 4;
            int c4 = (idx4 & 15) * 4;
            uint32_t so = (uint32_t)(r * SSTRIDE + c4) * 4;
            CP_ASYNC16(kb + so, &Kg[(j0 + r) * PD + c4]);
            // V rows permuted within each 8-block: smem row k holds key (k<4 ? 2k : 2k-7)
            int k = r & 7;
            int pr = (r & ~7) | ((k < 4) ? (k << 1) : ((k << 1) - 7));
            CP_ASYNC16(kb + KVBUF * 4 + so, &Vg[(j0 + pr) * PD + c4]);
        }
        CP_COMMIT();
    };

    issue_chunk(jbase, 0);

    const float LOG2E = 1.4426950408889634f;
    // stage Q tile (128 x 64), scaled by log2e
#pragma unroll
    for (int it = 0; it < 16; ++it) {
        int idx4 = tid + it * 128;
        int r = idx4 >> 4;
        int c4 = (idx4 & 15) * 4;
        float4 qv = *reinterpret_cast<const float4*>(&Qg[(i0 + r) * PD + c4]);
        *reinterpret_cast<float4*>(&Qs[r * SSTRIDE + c4]) =
            make_float4(qv.x * LOG2E, qv.y * LOG2E, qv.z * LOG2E, qv.w * LOG2E);
    }

    float lr[4] = {0.f, 0.f, 0.f, 0.f};  // per-lane partial row sums (reduced in epilogue)
    float Oacc[2][8][4];
#pragma unroll
    for (int t = 0; t < 2; ++t)
#pragma unroll
        for (int i = 0; i < 8; ++i) {
            Oacc[t][i][0] = 0.f; Oacc[t][i][1] = 0.f; Oacc[t][i][2] = 0.f; Oacc[t][i][3] = 0.f;
        }

    int buf = 0;
    for (int j0 = jbase; j0 < jend; j0 += 64) {
        CP_WAIT0();
        __syncthreads();
        if (j0 + 64 < jend) issue_chunk(j0 + 64, buf ^ 1);

        const float* Ks = sm + QROWS * SSTRIDE + buf * 2 * KVBUF;
        const float* Vs = Ks + KVBUF;

        // ---- S' = (log2e * Q) K^T : exact-split 3xTF32 ----
        float s[2][8][4];
#pragma unroll
        for (int t = 0; t < 2; ++t)
#pragma unroll
            for (int i = 0; i < 8; ++i) {
                s[t][i][0] = 0.f; s[t][i][1] = 0.f; s[t][i][2] = 0.f; s[t][i][3] = 0.f;
            }
#pragma unroll
        for (int kk = 0; kk < 8; ++kk) {
            const int k0 = kk * 8 + q4;
            uint32_t ah[2][4], al[2][4];
#pragma unroll
            for (int t = 0; t < 2; ++t) {
                const int rowA = w * 32 + t * 16 + r0;
                float a0f = Qs[rowA * SSTRIDE + k0];
                float a1f = Qs[(rowA + 8) * SSTRIDE + k0];
                float a2f = Qs[rowA * SSTRIDE + k0 + 4];
                float a3f = Qs[(rowA + 8) * SSTRIDE + k0 + 4];
                float h0 = trunc_hi(a0f), h1 = trunc_hi(a1f), h2 = trunc_hi(a2f), h3 = trunc_hi(a3f);
                ah[t][0] = __float_as_uint(h0); al[t][0] = __float_as_uint(a0f - h0);
                ah[t][1] = __float_as_uint(h1); al[t][1] = __float_as_uint(a1f - h1);
                ah[t][2] = __float_as_uint(h2); al[t][2] = __float_as_uint(a2f - h2);
                ah[t][3] = __float_as_uint(h3); al[t][3] = __float_as_uint(a3f - h3);
            }
#pragma unroll
            for (int nt = 0; nt < 8; ++nt) {
                float b0f = Ks[(nt * 8 + r0) * SSTRIDE + k0];
                float b1f = Ks[(nt * 8 + r0) * SSTRIDE + k0 + 4];
                float bh0f = trunc_hi(b0f), bh1f = trunc_hi(b1f);
                uint32_t bh0 = __float_as_uint(bh0f), bh1 = __float_as_uint(bh1f);
                uint32_t bl0 = __float_as_uint(b0f - bh0f), bl1 = __float_as_uint(b1f - bh1f);
#pragma unroll
                for (int t = 0; t < 2; ++t) {
                    mma8(s[t][nt], al[t][0], al[t][1], al[t][2], al[t][3], bh0, bh1);
                    mma8(s[t][nt], ah[t][0], ah[t][1], ah[t][2], ah[t][3], bl0, bl1);
                    mma8(s[t][nt], ah[t][0], ah[t][1], ah[t][2], ah[t][3], bh0, bh1);
                }
            }
        }

        // ---- p = 2^(S'); accumulate per-lane partial sums; P kept raw (HW truncates) ----
#pragma unroll
        for (int t = 0; t < 2; ++t) {
            float ps0 = 0.f, ps1 = 0.f;
#pragma unroll
            for (int nt = 0; nt < 8; ++nt) {
                float p0 = ex2f(s[t][nt][0]);
                float p1 = ex2f(s[t][nt][1]);
                float p2 = ex2f(s[t][nt][2]);
                float p3 = ex2f(s[t][nt][3]);
                ps0 += p0 + p1;
                ps1 += p2 + p3;
                s[t][nt][0] = p0;
                s[t][nt][1] = p1;
                s[t][nt][2] = p2;
                s[t][nt][3] = p3;
            }
            lr[2 * t] += ps0;
            lr[2 * t + 1] += ps1;
        }

        // ---- O += P V : A-frag IS the C-frag (V rows pre-permuted); V already tf32 ----
#pragma unroll
        for (int kk = 0; kk < 8; ++kk) {
#pragma unroll
            for (int dt = 0; dt < 8; ++dt) {
                uint32_t b0 = __float_as_uint(Vs[(kk * 8 + q4) * SSTRIDE + dt * 8 + r0]);
                uint32_t b1 = __float_as_uint(Vs[(kk * 8 + q4 + 4) * SSTRIDE + dt * 8 + r0]);
#pragma unroll
                for (int t = 0; t < 2; ++t)
                    mma8(Oacc[t][dt],
                         __float_as_uint(s[t][kk][0]), __float_as_uint(s[t][kk][2]),
                         __float_as_uint(s[t][kk][1]), __float_as_uint(s[t][kk][3]),
                         b0, b1);
            }
        }
        buf ^= 1;
    }

    // ---- epilogue: quad-reduce row sums once, write unnormalized O and l ----
#pragma unroll
    for (int i = 0; i < 4; ++i) {
        lr[i] += __shfl_xor_sync(0xffffffffu, lr[i], 1);
        lr[i] += __shfl_xor_sync(0xffffffffu, lr[i], 2);
    }
#pragma unroll
    for (int t = 0; t < 2; ++t) {
        const int orow = i0 + w * 32 + t * 16 + r0;
        if (q4 == 0) {
            Lg[orow] = lr[2 * t];
            Lg[orow + 8] = lr[2 * t + 1];
        }
#pragma unroll
        for (int dt = 0; dt < 8; ++dt) {
            *reinterpret_cast<float2*>(&Og[orow * PD + dt * 8 + 2 * q4]) =
                make_float2(Oacc[t][dt][0], Oacc[t][dt][1]);
            *reinterpret_cast<float2*>(&Og[(orow + 8) * PD + dt * 8 + 2 * q4]) =
                make_float2(Oacc[t][dt][2], Oacc[t][dt][3]);
        }
    }
}

// ===================== combine: out = (O0+O1+O2) / (l0+l1+l2) ============================
__global__ __launch_bounds__(256) void combine_kernel(float* __restrict__ out) {
    int idx4 = blockIdx.x * 256 + threadIdx.x;
    int fidx = idx4 * 4;
    int rowg = fidx >> 6;  // PD = 64
    float inv = 1.0f / (g_lpart[rowg] + g_lpart[LSZ + rowg] + g_lpart[2 * LSZ + rowg]);
    float4 a = *reinterpret_cast<const float4*>(&g_Opart[fidx]);
    float4 c = *reinterpret_cast<const float4*>(&g_Opart[ODSZ + fidx]);
    float4 d = *reinterpret_cast<const float4*>(&g_Opart[2 * ODSZ + fidx]);
    *reinterpret_cast<float4*>(&out[fidx]) =
        make_float4((a.x + c.x + d.x) * inv, (a.y + c.y + d.y) * inv,
                    (a.z + c.z + d.z) * inv, (a.w + c.w + d.w) * inv);
}

extern "C" void kernel_launch(void* const* d_in, const int* in_sizes, int n_in,
                              void* d_out, int out_size) {
    (void)in_sizes; (void)n_in; (void)out_size;
    const float* x1 = (const float*)d_in[0];
    const float* x2 = (const float*)d_in[1];
    const float* Wq = (const float*)d_in[2];
    const float* bq = (const float*)d_in[3];
    const float* Wkv = (const float*)d_in[4];
    const float* bkv = (const float*)d_in[5];
    float* out = (float*)d_out;

    const int proj_smem = PROJ_SMEM_FLOATS * sizeof(float);  // 55296
    cudaFuncSetAttribute(proj_kernel, cudaFuncAttributeMaxDynamicSharedMemorySize, proj_smem);
    cudaFuncSetAttribute(proj_kernel, cudaFuncAttributePreferredSharedMemoryCarveout, 100);
    proj_kernel<<<dim3(32, 36), 128, proj_smem>>>(x2, x1, Wq, bq, Wkv, bkv);

    const int smem_bytes = (QROWS * SSTRIDE + 4 * KVBUF) * sizeof(float);  // 104448
    cudaFuncSetAttribute(attn_kernel, cudaFuncAttributeMaxDynamicSharedMemorySize, smem_bytes);
    cudaFuncSetAttribute(attn_kernel, cudaFuncAttributePreferredSharedMemoryCarveout, 100);
    attn_kernel<<<dim3(NTOK / QROWS, HNUM, BATCH * NSPLIT), 128, smem_bytes>>>();

    combine_kernel<<<ODSZ / 4 / 256, 256>>>(out);
}